// round 1
// baseline (speedup 1.0000x reference)
#include <cuda_runtime.h>
#include <cstdint>
#include <math.h>

#define BDIM 32
#define LDIM 8
#define SDIM 512
#define DDIM 256
#define EDIM 2048
#define NTOK (BDIM*LDIM*SDIM)   /* 131072 */
#define TOKL (BDIM*SDIM)        /* 16384 tokens per l */

#define TM 128
#define TN 128
#define KB 8

// ---- device scratch (static allocation is allowed; dynamic is not) ----
__device__ float      g_embedT[(size_t)LDIM*EDIM*DDIM];   // (L,E,D) transposed codebook
__device__ float      g_enorm [(size_t)LDIM*EDIM];        // ||e||^2
__device__ int        g_ids   [NTOK];
__device__ int        g_counts[(size_t)LDIM*EDIM];
__device__ long long  g_sum   [(size_t)LDIM*DDIM*EDIM];   // fixed-point (x * 2^32) scatter sums
__device__ unsigned long long g_diffacc;                  // fixed-point (val * 2^20)
__device__ float      g_nvals [LDIM];

// ---------------------------------------------------------------------
// Transpose embed (L,D,E) -> g_embedT (L,E,D)
__global__ void k_transpose(const float* __restrict__ embed) {
    __shared__ float tile[32][33];
    int l  = blockIdx.z;
    int e0 = blockIdx.x * 32;
    int d0 = blockIdx.y * 32;
    int tx = threadIdx.x, ty = threadIdx.y;   // 32 x 8
    const float* src = embed + (size_t)l*DDIM*EDIM;
    #pragma unroll
    for (int i = ty; i < 32; i += 8)
        tile[i][tx] = src[(size_t)(d0+i)*EDIM + e0 + tx];
    __syncthreads();
    float* dst = g_embedT + (size_t)l*EDIM*DDIM;
    #pragma unroll
    for (int i = ty; i < 32; i += 8)
        dst[(size_t)(e0+i)*DDIM + d0 + tx] = tile[tx][i];
}

// ---------------------------------------------------------------------
// ||e||^2 per (l,e): coalesced across e
__global__ void k_enorm(const float* __restrict__ embed) {
    int idx = blockIdx.x*blockDim.x + threadIdx.x;   // l*E + e
    int l = idx / EDIM, e = idx % EDIM;
    const float* src = embed + (size_t)l*DDIM*EDIM + e;
    float s = 0.f;
    #pragma unroll 8
    for (int d = 0; d < DDIM; d++) {
        float v = src[(size_t)d*EDIM];
        s += v*v;
    }
    g_enorm[idx] = s;
}

// ---------------------------------------------------------------------
// Fused GEMM + argmin. Block: 256 threads (16x16), 8x8 microtile,
// tile = 128 tokens x 128 codes, loops all 16 code chunks keeping a
// running (min, idx) per token in shared memory.
__global__ void __launch_bounds__(256, 2)
k_assign(const float* __restrict__ x, const float* __restrict__ embed,
         float* __restrict__ out_ids_f) {
    __shared__ float As[KB][TM];
    __shared__ float Bs[KB][TN];
    __shared__ float sMin[TM];
    __shared__ int   sIdx[TM];
    __shared__ float redV[16][TM];
    __shared__ int   redI[16][TM];

    int l  = blockIdx.y;
    int r0 = blockIdx.x * TM;           // token tile within this l
    int b  = r0 / SDIM, s0 = r0 % SDIM; // all TM rows share b (TM divides S)
    const float* A  = x + ((size_t)(b*LDIM + l)*SDIM + s0) * DDIM;  // row stride D
    const float* Bm = embed + (size_t)l*DDIM*EDIM;                  // [d][e]
    const float* en = g_enorm + (size_t)l*EDIM;

    int tid = threadIdx.x;
    int tx = tid & 15, ty = tid >> 4;

    if (tid < TM) { sMin[tid] = 3.4e38f; sIdx[tid] = 0; }

    for (int n0 = 0; n0 < EDIM; n0 += TN) {
        float acc[8][8];
        #pragma unroll
        for (int i = 0; i < 8; i++)
            #pragma unroll
            for (int j = 0; j < 8; j++) acc[i][j] = 0.f;

        for (int kk = 0; kk < DDIM; kk += KB) {
            __syncthreads();
            {   // A tile: 128 rows x 8 k (transposed into smem)
                int row = tid >> 1, kq = (tid & 1) * 4;
                float4 v = *(const float4*)(A + (size_t)row*DDIM + kk + kq);
                As[kq+0][row] = v.x; As[kq+1][row] = v.y;
                As[kq+2][row] = v.z; As[kq+3][row] = v.w;
            }
            {   // B tile: 8 k x 128 codes (direct, coalesced)
                int k = tid >> 5, n = (tid & 31) * 4;
                *(float4*)&Bs[k][n] = *(const float4*)(Bm + (size_t)(kk+k)*EDIM + n0 + n);
            }
            __syncthreads();
            #pragma unroll
            for (int k = 0; k < KB; k++) {
                float a[8], bb[8];
                *(float4*)(a)    = *(const float4*)&As[k][ty*8];
                *(float4*)(a+4)  = *(const float4*)&As[k][ty*8+4];
                *(float4*)(bb)   = *(const float4*)&Bs[k][tx*8];
                *(float4*)(bb+4) = *(const float4*)&Bs[k][tx*8+4];
                #pragma unroll
                for (int i = 0; i < 8; i++)
                    #pragma unroll
                    for (int j = 0; j < 8; j++)
                        acc[i][j] += a[i]*bb[j];
            }
        }
        // scores = ||e||^2 - 2 x.e ; per-thread argmin over its 8 codes
        float en8[8];
        #pragma unroll
        for (int j = 0; j < 8; j++) en8[j] = en[n0 + tx*8 + j];
        #pragma unroll
        for (int i = 0; i < 8; i++) {
            float bv = 3.4e38f; int bi = 0;
            #pragma unroll
            for (int j = 0; j < 8; j++) {
                float sc = en8[j] - 2.0f*acc[i][j];
                int   n  = n0 + tx*8 + j;
                if (sc < bv) { bv = sc; bi = n; }
            }
            redV[tx][ty*8+i] = bv; redI[tx][ty*8+i] = bi;
        }
        __syncthreads();
        if (tid < TM) {   // merge 16 partials; keep FIRST index on ties
            float bv = sMin[tid]; int bi = sIdx[tid];
            #pragma unroll
            for (int t = 0; t < 16; t++) {
                float v = redV[t][tid]; int iv = redI[t][tid];
                if (v < bv || (v == bv && iv < bi)) { bv = v; bi = iv; }
            }
            sMin[tid] = bv; sIdx[tid] = bi;
        }
    }
    __syncthreads();
    if (tid < TM) {
        size_t gidx = (size_t)(b*LDIM + l)*SDIM + (s0 + tid);
        g_ids[gidx]     = sIdx[tid];
        out_ids_f[gidx] = (float)sIdx[tid];
    }
}

// ---------------------------------------------------------------------
// Fused: quantized output gather (out = q), fixed-point scatter of x into
// g_sum (L,D,E), count histogram, and diff accumulation for l == L-1.
// One block (256 threads) per token; thread = one d.
__global__ void k_scatter(const float* __restrict__ x, float* __restrict__ out) {
    int t = blockIdx.x;                 // token index in (B,L,S) order
    int l = (t / SDIM) % LDIM;
    int e = g_ids[t];
    int d = threadIdx.x;

    float xv = x[(size_t)t*DDIM + d];
    float qv = g_embedT[((size_t)l*EDIM + e)*DDIM + d];
    out[(size_t)t*DDIM + d] = qv;

    long long fx = llrint((double)xv * 4294967296.0);
    atomicAdd((unsigned long long*)&g_sum[((size_t)l*DDIM + d)*EDIM + e],
              (unsigned long long)fx);
    if (d == 0) atomicAdd(&g_counts[l*EDIM + e], 1);

    if (l == LDIM - 1) {
        __shared__ long long sred[8];
        float df = (qv - xv)*(qv - xv);
        long long fd = llrint((double)df * 1048576.0);
        #pragma unroll
        for (int o = 16; o > 0; o >>= 1) fd += __shfl_down_sync(0xffffffffu, fd, o);
        if ((threadIdx.x & 31) == 0) sred[threadIdx.x >> 5] = fd;
        __syncthreads();
        if (threadIdx.x == 0) {
            long long s = 0;
            #pragma unroll
            for (int w = 0; w < 8; w++) s += sred[w];
            atomicAdd(&g_diffacc, (unsigned long long)s);
        }
    }
}

// ---------------------------------------------------------------------
// Per-l: new_cluster_size, its sum n, and (block 0) the diff scalar.
__global__ void k_ncs(const float* __restrict__ cs_in,
                      float* __restrict__ out_ncs, float* __restrict__ out_diff) {
    int l = blockIdx.x;
    __shared__ float red[32];
    float local = 0.f;
    for (int e = threadIdx.x; e < EDIM; e += blockDim.x) {
        float v = 0.999f*cs_in[l*EDIM+e] + 0.001f*(float)g_counts[l*EDIM+e];
        out_ncs[l*EDIM+e] = v;
        local += v;
    }
    #pragma unroll
    for (int o = 16; o > 0; o >>= 1) local += __shfl_down_sync(0xffffffffu, local, o);
    if ((threadIdx.x & 31) == 0) red[threadIdx.x >> 5] = local;
    __syncthreads();
    if (threadIdx.x < 32) {
        float v = red[threadIdx.x];
        #pragma unroll
        for (int o = 16; o > 0; o >>= 1) v += __shfl_down_sync(0xffffffffu, v, o);
        if (threadIdx.x == 0) g_nvals[l] = v;
    }
    if (l == 0 && threadIdx.x == 0) {
        double dsum = (double)(long long)g_diffacc * (1.0/1048576.0);
        out_diff[0] = (float)(2.0 * (dsum / (double)((size_t)BDIM*SDIM*DDIM)) / (double)LDIM);
    }
}

// ---------------------------------------------------------------------
// new_embed_avg and new_embed over (L,D,E)
__global__ void k_final(const float* __restrict__ embed_avg,
                        const float* __restrict__ out_ncs,
                        float* __restrict__ out_ne, float* __restrict__ out_nea) {
    size_t i = (size_t)blockIdx.x*blockDim.x + threadIdx.x;
    int e = (int)(i % EDIM);
    int l = (int)(i / ((size_t)DDIM*EDIM));
    float sum = (float)((double)g_sum[i] * (1.0/4294967296.0));
    float nea = 0.999f*embed_avg[i] + 0.001f*sum;
    out_nea[i] = nea;
    float ncs = out_ncs[l*EDIM + e];
    float n   = g_nvals[l];
    float cs  = (ncs + 1e-5f) / (n + 0.02048f) * n;   // E*EPS = 2048e-5
    out_ne[i] = nea / cs;
}

// ---------------------------------------------------------------------
extern "C" void kernel_launch(void* const* d_in, const int* in_sizes, int n_in,
                              void* d_out, int out_size) {
    const float* x     = (const float*)d_in[0];
    const float* embed = (const float*)d_in[1];
    const float* csz   = (const float*)d_in[2];
    const float* eavg  = (const float*)d_in[3];

    float* out      = (float*)d_out;
    float* out_main = out;                               // (B,L,S,D)
    float* out_diff = out + (size_t)33554432;            // scalar
    float* out_ids  = out + (size_t)33554433;            // (B,L,S) as float
    float* out_ne   = out_ids + (size_t)131072;          // (L,D,E)
    float* out_ncs  = out_ne  + (size_t)4194304;         // (L,E)
    float* out_nea  = out_ncs + (size_t)16384;           // (L,D,E)

    void *pSum, *pCnt, *pDiff;
    cudaGetSymbolAddress(&pSum,  g_sum);
    cudaGetSymbolAddress(&pCnt,  g_counts);
    cudaGetSymbolAddress(&pDiff, g_diffacc);
    cudaMemsetAsync(pSum,  0, (size_t)LDIM*DDIM*EDIM*sizeof(long long));
    cudaMemsetAsync(pCnt,  0, (size_t)LDIM*EDIM*sizeof(int));
    cudaMemsetAsync(pDiff, 0, sizeof(unsigned long long));

    dim3 tb(32, 8);
    k_transpose<<<dim3(EDIM/32, DDIM/32, LDIM), tb>>>(embed);
    k_enorm<<<(LDIM*EDIM)/256, 256>>>(embed);
    k_assign<<<dim3(TOKL/TM, LDIM), 256>>>(x, embed, out_ids);
    k_scatter<<<NTOK, 256>>>(x, out_main);
    k_ncs<<<LDIM, 1024>>>(csz, out_ncs, out_diff);
    k_final<<<(unsigned)(((size_t)LDIM*DDIM*EDIM)/256), 256>>>(eavg, out_ncs, out_ne, out_nea);
}

// round 5
// speedup vs baseline: 1.3189x; 1.3189x over previous
#include <cuda_runtime.h>
#include <cuda_bf16.h>
#include <cstdint>
#include <math.h>

#define BDIM 32
#define LDIM 8
#define SDIM 512
#define DDIM 256
#define EDIM 2048
#define NTOK (BDIM*LDIM*SDIM)   /* 131072 */
#define TOKL (BDIM*SDIM)        /* 16384 tokens per l */

// ---- device scratch (static; dynamic alloc is forbidden) ----
__device__ float      g_embedT[(size_t)LDIM*EDIM*DDIM];   // (L,E,D) fp32 codebook for gather
__device__ float      g_enorm [(size_t)LDIM*EDIM];        // ||e||^2 (exact fp32)
__device__ int        g_ids   [NTOK];
__device__ int        g_counts[(size_t)LDIM*EDIM];
__device__ long long  g_sum   [(size_t)LDIM*DDIM*EDIM];   // fixed-point scatter sums
__device__ unsigned long long g_diffacc;
__device__ float      g_nvals [LDIM];
// bf16 split planes: x = A1+A2+A3, embed^T = B1+B2+B3 (per (l,e) row of 256 d)
__device__ unsigned short g_A1[(size_t)NTOK*DDIM];
__device__ unsigned short g_A2[(size_t)NTOK*DDIM];
__device__ unsigned short g_A3[(size_t)NTOK*DDIM];
__device__ unsigned short g_B1[(size_t)LDIM*EDIM*DDIM];
__device__ unsigned short g_B2[(size_t)LDIM*EDIM*DDIM];
__device__ unsigned short g_B3[(size_t)LDIM*EDIM*DDIM];

// =====================================================================
// PTX helpers (all baseline sm_80-level PTX -> compiles at compute_103)
// =====================================================================
__device__ __forceinline__ uint32_t smem_addr_u32(const void* p) {
    uint32_t a;
    asm("{ .reg .u64 t; cvta.to.shared.u64 t, %1; cvt.u32.u64 %0, t; }" : "=r"(a) : "l"(p));
    return a;
}
__device__ __forceinline__ void cpasync16(uint32_t s, const void* g) {
    asm volatile("cp.async.cg.shared.global [%0], [%1], 16;" :: "r"(s), "l"(g));
}
#define CP_COMMIT() asm volatile("cp.async.commit_group;" ::: "memory")
#define CP_WAIT(n)  asm volatile("cp.async.wait_group %0;" :: "n"(n) : "memory")

__device__ __forceinline__ void ldsm4(uint32_t* r, uint32_t addr) {
    asm volatile("ldmatrix.sync.aligned.m8n8.x4.shared.b16 {%0,%1,%2,%3}, [%4];"
        : "=r"(r[0]), "=r"(r[1]), "=r"(r[2]), "=r"(r[3]) : "r"(addr));
}
__device__ __forceinline__ void mma16816(float* c, const uint32_t* a, uint32_t b0, uint32_t b1) {
    asm volatile("mma.sync.aligned.m16n8k16.row.col.f32.bf16.bf16.f32 "
        "{%0,%1,%2,%3}, {%4,%5,%6,%7}, {%8,%9}, {%0,%1,%2,%3};"
        : "+f"(c[0]), "+f"(c[1]), "+f"(c[2]), "+f"(c[3])
        : "r"(a[0]), "r"(a[1]), "r"(a[2]), "r"(a[3]), "r"(b0), "r"(b1));
}

// =====================================================================
// bf16 3-way split
// =====================================================================
__device__ __forceinline__ void split3(float v, unsigned short& a, unsigned short& b,
                                       unsigned short& c) {
    __nv_bfloat16 h1 = __float2bfloat16(v);
    float r1 = v - __bfloat162float(h1);
    __nv_bfloat16 h2 = __float2bfloat16(r1);
    float r2 = r1 - __bfloat162float(h2);
    __nv_bfloat16 h3 = __float2bfloat16(r2);
    a = __bfloat16_as_ushort(h1);
    b = __bfloat16_as_ushort(h2);
    c = __bfloat16_as_ushort(h3);
}

// Expand x -> A planes (row-major, row stride 256)
__global__ void k_expand_x(const float* __restrict__ x) {
    int t = blockIdx.x;            // token
    int i = threadIdx.x;           // 128 threads, 2 d each
    float2 v = *(const float2*)(x + (size_t)t*DDIM + 2*i);
    unsigned short a0,b0,c0, a1,b1,c1;
    split3(v.x, a0, b0, c0);
    split3(v.y, a1, b1, c1);
    size_t o = (size_t)t*(DDIM/2) + i;
    ((uint32_t*)g_A1)[o] = (uint32_t)a0 | ((uint32_t)a1 << 16);
    ((uint32_t*)g_A2)[o] = (uint32_t)b0 | ((uint32_t)b1 << 16);
    ((uint32_t*)g_A3)[o] = (uint32_t)c0 | ((uint32_t)c1 << 16);
}

// Transpose + expand embed -> B planes + fp32 g_embedT (fused)
__global__ void k_expand_e(const float* __restrict__ embed) {
    __shared__ float tile[32][33];
    int l  = blockIdx.z;
    int e0 = blockIdx.x * 32;
    int d0 = blockIdx.y * 32;
    int tx = threadIdx.x, ty = threadIdx.y;   // 32 x 8
    const float* src = embed + (size_t)l*DDIM*EDIM;
    #pragma unroll
    for (int i = ty; i < 32; i += 8)
        tile[i][tx] = src[(size_t)(d0+i)*EDIM + e0 + tx];
    __syncthreads();
    #pragma unroll
    for (int i = ty; i < 32; i += 8) {
        float v = tile[tx][i];                // embed[l][d0+tx][e0+i]
        unsigned short h1, h2, h3;
        split3(v, h1, h2, h3);
        size_t idx = ((size_t)(l*EDIM + e0 + i))*DDIM + (d0 + tx);
        g_B1[idx] = h1; g_B2[idx] = h2; g_B3[idx] = h3;
        g_embedT[idx] = v;
    }
}

__global__ void k_enorm(const float* __restrict__ embed) {
    int idx = blockIdx.x*blockDim.x + threadIdx.x;
    int l = idx / EDIM, e = idx % EDIM;
    const float* src = embed + (size_t)l*DDIM*EDIM + e;
    float s = 0.f;
    #pragma unroll 8
    for (int d = 0; d < DDIM; d++) {
        float v = src[(size_t)d*EDIM];
        s += v*v;
    }
    g_enorm[idx] = s;
}

// =====================================================================
// HMMA fused GEMM + argmin
// Tile: 128 tokens x 256 codes. 256 threads = 8 warps (2 M x 4 N), warp 64x64.
// K loop: per 32-k slab load all 6 planes to smem (cp.async, double buffered),
// run the 6 split-product pairs. Rows padded to 40 bf16 (80B) -> conflict-free
// ldmatrix. Argmin carried in registers across the 8 N-tiles.
// =====================================================================
#define A_PLANE 10240             /* 128 rows * 80B */
#define B_OFF   30720             /* 3 A planes */
#define B_PLANE 20480             /* 256 rows * 80B */
#define STAGE_BYTES 92160         /* 3*A_PLANE + 3*B_PLANE */
#define SMEM_TOTAL (2*STAGE_BYTES)

__device__ __forceinline__ void load_slab(uint32_t st,
        const unsigned short* const* Ap, const unsigned short* const* Bp,
        int kcol, int n0, int tid) {
    #pragma unroll
    for (int p = 0; p < 3; p++) {
        #pragma unroll
        for (int it = 0; it < 2; it++) {       // 512 16B chunks for A plane
            int c = it*256 + tid, row = c >> 2, q = c & 3;
            cpasync16(st + p*A_PLANE + row*80 + q*16,
                      Ap[p] + (size_t)row*DDIM + kcol + q*8);
        }
    }
    #pragma unroll
    for (int p = 0; p < 3; p++) {
        #pragma unroll
        for (int it = 0; it < 4; it++) {       // 1024 chunks for B plane
            int c = it*256 + tid, row = c >> 2, q = c & 3;
            cpasync16(st + B_OFF + p*B_PLANE + row*80 + q*16,
                      Bp[p] + (size_t)(n0 + row)*DDIM + kcol + q*8);
        }
    }
}

__global__ void __launch_bounds__(256)
k_assign_mma(float* __restrict__ out_ids_f) {
    extern __shared__ unsigned char smem[];
    const uint32_t sb = smem_addr_u32(smem);
    int tid = threadIdx.x, lane = tid & 31, wid = tid >> 5;
    int wm = wid >> 2, wn = wid & 3;
    int l  = blockIdx.y;
    int r0 = blockIdx.x * 128;
    int b = r0 >> 9, s0 = r0 & 511;
    size_t tokbase = ((size_t)(b*LDIM + l)*SDIM + s0);

    const unsigned short* Ap[3] = { g_A1 + tokbase*DDIM, g_A2 + tokbase*DDIM, g_A3 + tokbase*DDIM };
    const unsigned short* Bp[3] = { g_B1 + (size_t)l*EDIM*DDIM, g_B2 + (size_t)l*EDIM*DDIM,
                                    g_B3 + (size_t)l*EDIM*DDIM };
    const float* en = g_enorm + l*EDIM;

    float bestv[8]; int besti[8];
    #pragma unroll
    for (int i = 0; i < 8; i++) { bestv[i] = 3.4e38f; besti[i] = 0; }

    const uint32_t aAddr = (uint32_t)((wm*64 + (lane & 15))*80 + (lane >> 4)*16);
    const uint32_t bAddr = (uint32_t)((wn*64 + (lane & 7) + ((lane >> 4) & 1)*8)*80
                                      + ((lane >> 3) & 1)*16);
    const int PA[6] = {0, 0, 1, 1, 0, 2};
    const int PB[6] = {0, 1, 0, 1, 2, 0};

    for (int n0 = 0; n0 < EDIM; n0 += 256) {
        float acc[4][8][4];
        #pragma unroll
        for (int mf = 0; mf < 4; mf++)
            #pragma unroll
            for (int nf = 0; nf < 8; nf++)
                #pragma unroll
                for (int q = 0; q < 4; q++) acc[mf][nf][q] = 0.f;

        load_slab(sb, Ap, Bp, 0, n0, tid);
        CP_COMMIT();

        for (int ks = 0; ks < 8; ks++) {
            int st = ks & 1;
            if (ks < 7) {
                load_slab(sb + (st^1)*STAGE_BYTES, Ap, Bp, (ks+1)*32, n0, tid);
                CP_COMMIT();
                CP_WAIT(1);
            } else {
                CP_WAIT(0);
            }
            __syncthreads();
            uint32_t stB = sb + st*STAGE_BYTES;
            #pragma unroll
            for (int pr = 0; pr < 6; pr++) {
                uint32_t aP = stB + PA[pr]*A_PLANE + aAddr;
                uint32_t bP = stB + B_OFF + PB[pr]*B_PLANE + bAddr;
                #pragma unroll
                for (int kq = 0; kq < 2; kq++) {
                    uint32_t a[4][4], bf[4][4];
                    #pragma unroll
                    for (int mf = 0; mf < 4; mf++) ldsm4(a[mf],  aP + mf*1280 + kq*32);
                    #pragma unroll
                    for (int nf = 0; nf < 4; nf++) ldsm4(bf[nf], bP + nf*1280 + kq*32);
                    #pragma unroll
                    for (int mf = 0; mf < 4; mf++)
                        #pragma unroll
                        for (int nf = 0; nf < 4; nf++) {
                            mma16816(acc[mf][2*nf],   a[mf], bf[nf][0], bf[nf][1]);
                            mma16816(acc[mf][2*nf+1], a[mf], bf[nf][2], bf[nf][3]);
                        }
                }
            }
            __syncthreads();
        }

        // fold scores of this 256-code tile into running argmin
        #pragma unroll
        for (int mf = 0; mf < 4; mf++)
            #pragma unroll
            for (int nf = 0; nf < 8; nf++) {
                int col = n0 + wn*64 + nf*8 + 2*(lane & 3);
                float e0 = en[col], e1 = en[col + 1];
                #pragma unroll
                for (int h = 0; h < 2; h++) {
                    int slot = mf*2 + h;
                    float v0 = fmaf(-2.0f, acc[mf][nf][2*h],     e0);
                    float v1 = fmaf(-2.0f, acc[mf][nf][2*h + 1], e1);
                    if (v0 < bestv[slot] || (v0 == bestv[slot] && col   < besti[slot]))
                        { bestv[slot] = v0; besti[slot] = col; }
                    if (v1 < bestv[slot] || (v1 == bestv[slot] && col+1 < besti[slot]))
                        { bestv[slot] = v1; besti[slot] = col + 1; }
                }
            }
    }

    __syncthreads();
    float* redV = (float*)smem;
    int*   redI = (int*)(smem + 128*16*sizeof(float));
    int slot16 = wn*4 + (lane & 3);
    #pragma unroll
    for (int mf = 0; mf < 4; mf++)
        #pragma unroll
        for (int h = 0; h < 2; h++) {
            int r = wm*64 + mf*16 + (lane >> 2) + h*8;
            redV[r*16 + slot16] = bestv[mf*2 + h];
            redI[r*16 + slot16] = besti[mf*2 + h];
        }
    __syncthreads();
    if (tid < 128) {
        float bv = 3.4e38f; int bi = 0;
        #pragma unroll
        for (int s = 0; s < 16; s++) {
            float v = redV[tid*16 + s]; int iv = redI[tid*16 + s];
            if (v < bv || (v == bv && iv < bi)) { bv = v; bi = iv; }
        }
        size_t gidx = tokbase + tid;
        g_ids[gidx]     = bi;
        out_ids_f[gidx] = (float)bi;
    }
}

// =====================================================================
// scatter / tail kernels (unchanged from the passing round-1 version)
// =====================================================================
__global__ void k_scatter(const float* __restrict__ x, float* __restrict__ out) {
    int t = blockIdx.x;
    int l = (t / SDIM) % LDIM;
    int e = g_ids[t];
    int d = threadIdx.x;

    float xv = x[(size_t)t*DDIM + d];
    float qv = g_embedT[((size_t)l*EDIM + e)*DDIM + d];
    out[(size_t)t*DDIM + d] = qv;

    long long fx = llrint((double)xv * 4294967296.0);
    atomicAdd((unsigned long long*)&g_sum[((size_t)l*DDIM + d)*EDIM + e],
              (unsigned long long)fx);
    if (d == 0) atomicAdd(&g_counts[l*EDIM + e], 1);

    if (l == LDIM - 1) {
        __shared__ long long sred[8];
        float df = (qv - xv)*(qv - xv);
        long long fd = llrint((double)df * 1048576.0);
        #pragma unroll
        for (int o = 16; o > 0; o >>= 1) fd += __shfl_down_sync(0xffffffffu, fd, o);
        if ((threadIdx.x & 31) == 0) sred[threadIdx.x >> 5] = fd;
        __syncthreads();
        if (threadIdx.x == 0) {
            long long s = 0;
            #pragma unroll
            for (int w = 0; w < 8; w++) s += sred[w];
            atomicAdd(&g_diffacc, (unsigned long long)s);
        }
    }
}

__global__ void k_ncs(const float* __restrict__ cs_in,
                      float* __restrict__ out_ncs, float* __restrict__ out_diff) {
    int l = blockIdx.x;
    __shared__ float red[32];
    float local = 0.f;
    for (int e = threadIdx.x; e < EDIM; e += blockDim.x) {
        float v = 0.999f*cs_in[l*EDIM+e] + 0.001f*(float)g_counts[l*EDIM+e];
        out_ncs[l*EDIM+e] = v;
        local += v;
    }
    #pragma unroll
    for (int o = 16; o > 0; o >>= 1) local += __shfl_down_sync(0xffffffffu, local, o);
    if ((threadIdx.x & 31) == 0) red[threadIdx.x >> 5] = local;
    __syncthreads();
    if (threadIdx.x < 32) {
        float v = red[threadIdx.x];
        #pragma unroll
        for (int o = 16; o > 0; o >>= 1) v += __shfl_down_sync(0xffffffffu, v, o);
        if (threadIdx.x == 0) g_nvals[l] = v;
    }
    if (l == 0 && threadIdx.x == 0) {
        double dsum = (double)(long long)g_diffacc * (1.0/1048576.0);
        out_diff[0] = (float)(2.0 * (dsum / (double)((size_t)BDIM*SDIM*DDIM)) / (double)LDIM);
    }
}

__global__ void k_final(const float* __restrict__ embed_avg,
                        const float* __restrict__ out_ncs,
                        float* __restrict__ out_ne, float* __restrict__ out_nea) {
    size_t i = (size_t)blockIdx.x*blockDim.x + threadIdx.x;
    int e = (int)(i % EDIM);
    int l = (int)(i / ((size_t)DDIM*EDIM));
    float sum = (float)((double)g_sum[i] * (1.0/4294967296.0));
    float nea = 0.999f*embed_avg[i] + 0.001f*sum;
    out_nea[i] = nea;
    float ncs = out_ncs[l*EDIM + e];
    float n   = g_nvals[l];
    float cs  = (ncs + 1e-5f) / (n + 0.02048f) * n;
    out_ne[i] = nea / cs;
}

// =====================================================================
extern "C" void kernel_launch(void* const* d_in, const int* in_sizes, int n_in,
                              void* d_out, int out_size) {
    const float* x     = (const float*)d_in[0];
    const float* embed = (const float*)d_in[1];
    const float* csz   = (const float*)d_in[2];
    const float* eavg  = (const float*)d_in[3];

    float* out      = (float*)d_out;
    float* out_main = out;
    float* out_diff = out + (size_t)33554432;
    float* out_ids  = out + (size_t)33554433;
    float* out_ne   = out_ids + (size_t)131072;
    float* out_ncs  = out_ne  + (size_t)4194304;
    float* out_nea  = out_ncs + (size_t)16384;

    cudaFuncSetAttribute(k_assign_mma, cudaFuncAttributeMaxDynamicSharedMemorySize,
                         SMEM_TOTAL);

    void *pSum, *pCnt, *pDiff;
    cudaGetSymbolAddress(&pSum,  g_sum);
    cudaGetSymbolAddress(&pCnt,  g_counts);
    cudaGetSymbolAddress(&pDiff, g_diffacc);
    cudaMemsetAsync(pSum,  0, (size_t)LDIM*DDIM*EDIM*sizeof(long long));
    cudaMemsetAsync(pCnt,  0, (size_t)LDIM*EDIM*sizeof(int));
    cudaMemsetAsync(pDiff, 0, sizeof(unsigned long long));

    dim3 tb(32, 8);
    k_enorm<<<(LDIM*EDIM)/256, 256>>>(embed);
    k_expand_x<<<NTOK, 128>>>(x);
    k_expand_e<<<dim3(EDIM/32, DDIM/32, LDIM), tb>>>(embed);
    k_assign_mma<<<dim3(TOKL/128, LDIM), 256, SMEM_TOTAL>>>(out_ids);
    k_scatter<<<NTOK, 256>>>(x, out_main);
    k_ncs<<<LDIM, 1024>>>(csz, out_ncs, out_diff);
    k_final<<<(unsigned)(((size_t)LDIM*DDIM*EDIM)/256), 256>>>(eavg, out_ncs, out_ne, out_nea);
}

// round 6
// speedup vs baseline: 1.9413x; 1.4719x over previous
#include <cuda_runtime.h>
#include <cuda_bf16.h>
#include <cstdint>
#include <math.h>

#define BDIM 32
#define LDIM 8
#define SDIM 512
#define DDIM 256
#define EDIM 2048
#define NTOK (BDIM*LDIM*SDIM)   /* 131072 */
#define TOKL (BDIM*SDIM)        /* 16384 tokens per l */

// ---- device scratch ----
__device__ float      g_embedT[(size_t)LDIM*EDIM*DDIM];   // (L,E,D) fp32 codebook
__device__ float      g_enorm [(size_t)LDIM*EDIM];        // ||e||^2 fp32
__device__ int        g_ids   [NTOK];
__device__ int2       g_cand  [NTOK];                     // top-2 approx candidates
__device__ int        g_counts[(size_t)LDIM*EDIM];
__device__ long long  g_sum   [(size_t)LDIM*DDIM*EDIM];
__device__ unsigned long long g_diffacc;
__device__ float      g_nvals [LDIM];
// bf16 2-split planes
__device__ unsigned short g_A1[(size_t)NTOK*DDIM];
__device__ unsigned short g_A2[(size_t)NTOK*DDIM];
__device__ unsigned short g_B1[(size_t)LDIM*EDIM*DDIM];
__device__ unsigned short g_B2[(size_t)LDIM*EDIM*DDIM];

// =====================================================================
__device__ __forceinline__ uint32_t smem_addr_u32(const void* p) {
    uint32_t a;
    asm("{ .reg .u64 t; cvta.to.shared.u64 t, %1; cvt.u32.u64 %0, t; }" : "=r"(a) : "l"(p));
    return a;
}
__device__ __forceinline__ void cpasync16(uint32_t s, const void* g) {
    asm volatile("cp.async.cg.shared.global [%0], [%1], 16;" :: "r"(s), "l"(g));
}
#define CP_COMMIT() asm volatile("cp.async.commit_group;" ::: "memory")
#define CP_WAIT(n)  asm volatile("cp.async.wait_group %0;" :: "n"(n) : "memory")

__device__ __forceinline__ void ldsm4(uint32_t* r, uint32_t addr) {
    asm volatile("ldmatrix.sync.aligned.m8n8.x4.shared.b16 {%0,%1,%2,%3}, [%4];"
        : "=r"(r[0]), "=r"(r[1]), "=r"(r[2]), "=r"(r[3]) : "r"(addr));
}
__device__ __forceinline__ void mma16816(float* c, const uint32_t* a, uint32_t b0, uint32_t b1) {
    asm volatile("mma.sync.aligned.m16n8k16.row.col.f32.bf16.bf16.f32 "
        "{%0,%1,%2,%3}, {%4,%5,%6,%7}, {%8,%9}, {%0,%1,%2,%3};"
        : "+f"(c[0]), "+f"(c[1]), "+f"(c[2]), "+f"(c[3])
        : "r"(a[0]), "r"(a[1]), "r"(a[2]), "r"(a[3]), "r"(b0), "r"(b1));
}

__device__ __forceinline__ void split2(float v, unsigned short& a, unsigned short& b) {
    __nv_bfloat16 h1 = __float2bfloat16(v);
    float r1 = v - __bfloat162float(h1);
    __nv_bfloat16 h2 = __float2bfloat16(r1);
    a = __bfloat16_as_ushort(h1);
    b = __bfloat16_as_ushort(h2);
}

// Expand x -> A1, A2
__global__ void k_expand_x(const float* __restrict__ x) {
    int t = blockIdx.x;
    int i = threadIdx.x;           // 128 threads, 2 d each
    float2 v = *(const float2*)(x + (size_t)t*DDIM + 2*i);
    unsigned short a0,b0, a1,b1;
    split2(v.x, a0, b0);
    split2(v.y, a1, b1);
    size_t o = (size_t)t*(DDIM/2) + i;
    ((uint32_t*)g_A1)[o] = (uint32_t)a0 | ((uint32_t)a1 << 16);
    ((uint32_t*)g_A2)[o] = (uint32_t)b0 | ((uint32_t)b1 << 16);
}

// Transpose + expand embed -> B1, B2 + fp32 g_embedT
__global__ void k_expand_e(const float* __restrict__ embed) {
    __shared__ float tile[32][33];
    int l  = blockIdx.z;
    int e0 = blockIdx.x * 32;
    int d0 = blockIdx.y * 32;
    int tx = threadIdx.x, ty = threadIdx.y;   // 32 x 8
    const float* src = embed + (size_t)l*DDIM*EDIM;
    #pragma unroll
    for (int i = ty; i < 32; i += 8)
        tile[i][tx] = src[(size_t)(d0+i)*EDIM + e0 + tx];
    __syncthreads();
    #pragma unroll
    for (int i = ty; i < 32; i += 8) {
        float v = tile[tx][i];
        unsigned short h1, h2;
        split2(v, h1, h2);
        size_t idx = ((size_t)(l*EDIM + e0 + i))*DDIM + (d0 + tx);
        g_B1[idx] = h1; g_B2[idx] = h2;
        g_embedT[idx] = v;
    }
}

__global__ void k_enorm(const float* __restrict__ embed) {
    int idx = blockIdx.x*blockDim.x + threadIdx.x;
    int l = idx / EDIM, e = idx % EDIM;
    const float* src = embed + (size_t)l*DDIM*EDIM + e;
    float s = 0.f;
    #pragma unroll 8
    for (int d = 0; d < DDIM; d++) {
        float v = src[(size_t)d*EDIM];
        s += v*v;
    }
    g_enorm[idx] = s;
}

// =====================================================================
// HMMA fused GEMM + approx top-2.
// 128 tokens x 2048 codes per CTA; N-tiles of 256, k-slabs of 32.
// A (2 planes, full K=256) resident in SMEM, 528B row stride (conflict-free).
// B (2 planes) double-buffered 80B-row slabs. 3 products: A1B1+A1B2+A2B1.
// =====================================================================
#define A_PLANE_FULL 67584            /* 128 * 528 */
#define B_STAGE_OFF  135168           /* 2 * A_PLANE_FULL */
#define B_PLANE      20480            /* 256 * 80 */
#define B_STAGE      40960            /* 2 planes */
#define SMEM_TOTAL   217088           /* B_STAGE_OFF + 2*B_STAGE */

__device__ __forceinline__ void load_Bslab(uint32_t dst,
        const unsigned short* B1r, const unsigned short* B2r, int g, int tid) {
    int n0 = (g >> 3) << 8, kcol = (g & 7) << 5;
    #pragma unroll
    for (int it = 0; it < 4; it++) {
        int c = it*256 + tid, row = c >> 2, q = c & 3;
        cpasync16(dst + row*80 + q*16, B1r + (size_t)(n0+row)*DDIM + kcol + q*8);
    }
    #pragma unroll
    for (int it = 0; it < 4; it++) {
        int c = it*256 + tid, row = c >> 2, q = c & 3;
        cpasync16(dst + B_PLANE + row*80 + q*16, B2r + (size_t)(n0+row)*DDIM + kcol + q*8);
    }
}

__global__ void __launch_bounds__(256)
k_assign_mma(int dummy) {
    extern __shared__ unsigned char smem[];
    const uint32_t sb = smem_addr_u32(smem);
    int tid = threadIdx.x, lane = tid & 31, wid = tid >> 5;
    int wm = wid >> 2, wn = wid & 3;
    int l  = blockIdx.y;
    int r0 = blockIdx.x * 128;
    int b = r0 >> 9, s0 = r0 & 511;
    size_t tokbase = ((size_t)(b*LDIM + l)*SDIM + s0);

    const unsigned short* A1r = g_A1 + tokbase*DDIM;
    const unsigned short* A2r = g_A2 + tokbase*DDIM;
    const unsigned short* B1r = g_B1 + (size_t)l*EDIM*DDIM;
    const unsigned short* B2r = g_B2 + (size_t)l*EDIM*DDIM;
    const float* en = g_enorm + l*EDIM;

    // prologue: A full-K (both planes) + B slab 0 | B slab 1
    #pragma unroll
    for (int it = 0; it < 16; it++) {
        int c = it*256 + tid, row = c >> 5, q = c & 31;
        cpasync16(sb + row*528 + q*16, A1r + (size_t)row*DDIM + q*8);
    }
    #pragma unroll
    for (int it = 0; it < 16; it++) {
        int c = it*256 + tid, row = c >> 5, q = c & 31;
        cpasync16(sb + A_PLANE_FULL + row*528 + q*16, A2r + (size_t)row*DDIM + q*8);
    }
    load_Bslab(sb + B_STAGE_OFF, B1r, B2r, 0, tid);
    CP_COMMIT();
    load_Bslab(sb + B_STAGE_OFF + B_STAGE, B1r, B2r, 1, tid);
    CP_COMMIT();

    float bv0[8], bv1[8]; int bi0[8], bi1[8];
    #pragma unroll
    for (int i = 0; i < 8; i++) { bv0[i] = 3.4e38f; bv1[i] = 3.4e38f; bi0[i] = 0; bi1[i] = 0; }

    const uint32_t aAddrBase = (uint32_t)((wm*64 + (lane & 15))*528 + (lane >> 4)*16);
    const uint32_t bAddrBase = (uint32_t)((wn*64 + (lane & 7) + ((lane >> 4) & 1)*8)*80
                                          + ((lane >> 3) & 1)*16);
    float acc[4][8][4];

    for (int g = 0; g < 64; g++) {
        int ks = g & 7;
        if (ks == 0) {
            #pragma unroll
            for (int mf = 0; mf < 4; mf++)
                #pragma unroll
                for (int nf = 0; nf < 8; nf++)
                    #pragma unroll
                    for (int q = 0; q < 4; q++) acc[mf][nf][q] = 0.f;
        }
        if (g == 63) { CP_WAIT(0); } else { CP_WAIT(1); }
        __syncthreads();
        if (g + 1 < 64) {
            load_Bslab(sb + B_STAGE_OFF + ((g+1) & 1)*B_STAGE, B1r, B2r, g+1, tid);
            CP_COMMIT();
        }
        uint32_t aBase = sb + aAddrBase + ks*64;
        uint32_t bBase = sb + B_STAGE_OFF + (g & 1)*B_STAGE + bAddrBase;
        #pragma unroll
        for (int kq = 0; kq < 2; kq++) {
            uint32_t a[4][4], bf[4][4], bf2[4][4];
            #pragma unroll
            for (int mf = 0; mf < 4; mf++) ldsm4(a[mf],   aBase + mf*8448 + kq*32);
            #pragma unroll
            for (int nf = 0; nf < 4; nf++) ldsm4(bf[nf],  bBase + nf*1280 + kq*32);
            #pragma unroll
            for (int nf = 0; nf < 4; nf++) ldsm4(bf2[nf], bBase + B_PLANE + nf*1280 + kq*32);
            #pragma unroll
            for (int mf = 0; mf < 4; mf++)
                #pragma unroll
                for (int nf = 0; nf < 4; nf++) {
                    mma16816(acc[mf][2*nf],   a[mf], bf[nf][0],  bf[nf][1]);
                    mma16816(acc[mf][2*nf+1], a[mf], bf[nf][2],  bf[nf][3]);
                    mma16816(acc[mf][2*nf],   a[mf], bf2[nf][0], bf2[nf][1]);
                    mma16816(acc[mf][2*nf+1], a[mf], bf2[nf][2], bf2[nf][3]);
                }
            #pragma unroll
            for (int mf = 0; mf < 4; mf++) ldsm4(a[mf], aBase + A_PLANE_FULL + mf*8448 + kq*32);
            #pragma unroll
            for (int mf = 0; mf < 4; mf++)
                #pragma unroll
                for (int nf = 0; nf < 4; nf++) {
                    mma16816(acc[mf][2*nf],   a[mf], bf[nf][0], bf[nf][1]);
                    mma16816(acc[mf][2*nf+1], a[mf], bf[nf][2], bf[nf][3]);
                }
        }
        if (ks == 7) {
            int n0 = (g >> 3) << 8;
            #pragma unroll
            for (int nf = 0; nf < 8; nf++) {
                int col = n0 + wn*64 + nf*8 + 2*(lane & 3);
                float e0 = en[col], e1 = en[col + 1];
                #pragma unroll
                for (int mf = 0; mf < 4; mf++)
                    #pragma unroll
                    for (int h = 0; h < 2; h++) {
                        int s = mf*2 + h;
                        float v0 = fmaf(-2.0f, acc[mf][nf][2*h],     e0);
                        float v1 = fmaf(-2.0f, acc[mf][nf][2*h + 1], e1);
                        if (v0 < bv0[s]) { bv1[s]=bv0[s]; bi1[s]=bi0[s]; bv0[s]=v0; bi0[s]=col; }
                        else if (v0 < bv1[s]) { bv1[s]=v0; bi1[s]=col; }
                        if (v1 < bv0[s]) { bv1[s]=bv0[s]; bi1[s]=bi0[s]; bv0[s]=v1; bi0[s]=col+1; }
                        else if (v1 < bv1[s]) { bv1[s]=v1; bi1[s]=col+1; }
                    }
            }
        }
    }

    __syncthreads();
    float* redV = (float*)smem;                 // [128][16][2]
    int*   redI = (int*)(smem + 16384);
    int slot16 = wn*4 + (lane & 3);
    #pragma unroll
    for (int mf = 0; mf < 4; mf++)
        #pragma unroll
        for (int h = 0; h < 2; h++) {
            int s = mf*2 + h;
            int r = wm*64 + mf*16 + (lane >> 2) + h*8;
            redV[(r*16 + slot16)*2 + 0] = bv0[s];
            redV[(r*16 + slot16)*2 + 1] = bv1[s];
            redI[(r*16 + slot16)*2 + 0] = bi0[s];
            redI[(r*16 + slot16)*2 + 1] = bi1[s];
        }
    __syncthreads();
    if (tid < 128) {
        float b0 = 3.4e38f, b1v = 3.4e38f; int i0 = 0, i1 = 0;
        #pragma unroll
        for (int s = 0; s < 32; s++) {
            float v = redV[tid*32 + s]; int iv = redI[tid*32 + s];
            if (v < b0 || (v == b0 && iv < i0)) { b1v = b0; i1 = i0; b0 = v; i0 = iv; }
            else if ((v < b1v || (v == b1v && iv < i1)) && iv != i0) { b1v = v; i1 = iv; }
        }
        g_cand[tokbase + tid] = make_int2(i0, i1);
    }
}

// =====================================================================
// Exact fp32 rescore of the two candidates -> final ids
// =====================================================================
__global__ void k_rescore(const float* __restrict__ x, float* __restrict__ out_ids_f) {
    int w = threadIdx.x >> 5, lane = threadIdx.x & 31;
    int t = blockIdx.x*8 + w;
    int l = (t / SDIM) % LDIM;
    int2 c = g_cand[t];
    const float* xr = x + (size_t)t*DDIM;
    const float* e0 = g_embedT + ((size_t)l*EDIM + c.x)*DDIM;
    const float* e1 = g_embedT + ((size_t)l*EDIM + c.y)*DDIM;
    float d0 = 0.f, d1 = 0.f;
    #pragma unroll
    for (int i = 0; i < 8; i++) {
        float xv = xr[lane + 32*i];
        d0 += xv * e0[lane + 32*i];
        d1 += xv * e1[lane + 32*i];
    }
    #pragma unroll
    for (int o = 16; o > 0; o >>= 1) {
        d0 += __shfl_down_sync(0xffffffffu, d0, o);
        d1 += __shfl_down_sync(0xffffffffu, d1, o);
    }
    if (lane == 0) {
        const float* en = g_enorm + l*EDIM;
        float s0 = fmaf(-2.0f, d0, en[c.x]);
        float s1 = fmaf(-2.0f, d1, en[c.y]);
        int best = (s1 < s0 || (s1 == s0 && c.y < c.x)) ? c.y : c.x;
        g_ids[t] = best;
        out_ids_f[t] = (float)best;
    }
}

// =====================================================================
// scatter / tail kernels (unchanged, known-good)
// =====================================================================
__global__ void k_scatter(const float* __restrict__ x, float* __restrict__ out) {
    int t = blockIdx.x;
    int l = (t / SDIM) % LDIM;
    int e = g_ids[t];
    int d = threadIdx.x;

    float xv = x[(size_t)t*DDIM + d];
    float qv = g_embedT[((size_t)l*EDIM + e)*DDIM + d];
    out[(size_t)t*DDIM + d] = qv;

    long long fx = llrint((double)xv * 4294967296.0);
    atomicAdd((unsigned long long*)&g_sum[((size_t)l*DDIM + d)*EDIM + e],
              (unsigned long long)fx);
    if (d == 0) atomicAdd(&g_counts[l*EDIM + e], 1);

    if (l == LDIM - 1) {
        __shared__ long long sred[8];
        float df = (qv - xv)*(qv - xv);
        long long fd = llrint((double)df * 1048576.0);
        #pragma unroll
        for (int o = 16; o > 0; o >>= 1) fd += __shfl_down_sync(0xffffffffu, fd, o);
        if ((threadIdx.x & 31) == 0) sred[threadIdx.x >> 5] = fd;
        __syncthreads();
        if (threadIdx.x == 0) {
            long long s = 0;
            #pragma unroll
            for (int w = 0; w < 8; w++) s += sred[w];
            atomicAdd(&g_diffacc, (unsigned long long)s);
        }
    }
}

__global__ void k_ncs(const float* __restrict__ cs_in,
                      float* __restrict__ out_ncs, float* __restrict__ out_diff) {
    int l = blockIdx.x;
    __shared__ float red[32];
    float local = 0.f;
    for (int e = threadIdx.x; e < EDIM; e += blockDim.x) {
        float v = 0.999f*cs_in[l*EDIM+e] + 0.001f*(float)g_counts[l*EDIM+e];
        out_ncs[l*EDIM+e] = v;
        local += v;
    }
    #pragma unroll
    for (int o = 16; o > 0; o >>= 1) local += __shfl_down_sync(0xffffffffu, local, o);
    if ((threadIdx.x & 31) == 0) red[threadIdx.x >> 5] = local;
    __syncthreads();
    if (threadIdx.x < 32) {
        float v = red[threadIdx.x];
        #pragma unroll
        for (int o = 16; o > 0; o >>= 1) v += __shfl_down_sync(0xffffffffu, v, o);
        if (threadIdx.x == 0) g_nvals[l] = v;
    }
    if (l == 0 && threadIdx.x == 0) {
        double dsum = (double)(long long)g_diffacc * (1.0/1048576.0);
        out_diff[0] = (float)(2.0 * (dsum / (double)((size_t)BDIM*SDIM*DDIM)) / (double)LDIM);
    }
}

__global__ void k_final(const float* __restrict__ embed_avg,
                        const float* __restrict__ out_ncs,
                        float* __restrict__ out_ne, float* __restrict__ out_nea) {
    size_t i = (size_t)blockIdx.x*blockDim.x + threadIdx.x;
    int e = (int)(i % EDIM);
    int l = (int)(i / ((size_t)DDIM*EDIM));
    float sum = (float)((double)g_sum[i] * (1.0/4294967296.0));
    float nea = 0.999f*embed_avg[i] + 0.001f*sum;
    out_nea[i] = nea;
    float ncs = out_ncs[l*EDIM + e];
    float n   = g_nvals[l];
    float cs  = (ncs + 1e-5f) / (n + 0.02048f) * n;
    out_ne[i] = nea / cs;
}

// =====================================================================
extern "C" void kernel_launch(void* const* d_in, const int* in_sizes, int n_in,
                              void* d_out, int out_size) {
    const float* x     = (const float*)d_in[0];
    const float* embed = (const float*)d_in[1];
    const float* csz   = (const float*)d_in[2];
    const float* eavg  = (const float*)d_in[3];

    float* out      = (float*)d_out;
    float* out_main = out;
    float* out_diff = out + (size_t)33554432;
    float* out_ids  = out + (size_t)33554433;
    float* out_ne   = out_ids + (size_t)131072;
    float* out_ncs  = out_ne  + (size_t)4194304;
    float* out_nea  = out_ncs + (size_t)16384;

    cudaFuncSetAttribute(k_assign_mma, cudaFuncAttributeMaxDynamicSharedMemorySize,
                         SMEM_TOTAL);

    void *pSum, *pCnt, *pDiff;
    cudaGetSymbolAddress(&pSum,  g_sum);
    cudaGetSymbolAddress(&pCnt,  g_counts);
    cudaGetSymbolAddress(&pDiff, g_diffacc);
    cudaMemsetAsync(pSum,  0, (size_t)LDIM*DDIM*EDIM*sizeof(long long));
    cudaMemsetAsync(pCnt,  0, (size_t)LDIM*EDIM*sizeof(int));
    cudaMemsetAsync(pDiff, 0, sizeof(unsigned long long));

    dim3 tb(32, 8);
    k_enorm<<<(LDIM*EDIM)/256, 256>>>(embed);
    k_expand_x<<<NTOK, 128>>>(x);
    k_expand_e<<<dim3(EDIM/32, DDIM/32, LDIM), tb>>>(embed);
    k_assign_mma<<<dim3(TOKL/128, LDIM), 256, SMEM_TOTAL>>>(0);
    k_rescore<<<NTOK/8, 256>>>(x, out_ids);
    k_scatter<<<NTOK, 256>>>(x, out_main);
    k_ncs<<<LDIM, 1024>>>(csz, out_ncs, out_diff);
    k_final<<<(unsigned)(((size_t)LDIM*DDIM*EDIM)/256), 256>>>(eavg, out_ncs, out_ne, out_nea);
}